// round 8
// baseline (speedup 1.0000x reference)
#include <cuda_runtime.h>
#include <cstdint>

#define D_DIM 128

// ---------------- device scratch: single struct -> one memset ----------------
// 16B-aligned arrays FIRST (float4 loads on M/W), counters last.
struct alignas(16) Scratch {
    float  M[D_DIM * D_DIM];            // M = U U^T            (offset 0)
    float  W[D_DIM * D_DIM];            // W = U diag(cnt) U^T  (offset 64KB)
    float  cnt[4096];                   // histogram of G
    double acc;                         // dots accumulator
    unsigned histdone;                  // blocks finished hist phase
    unsigned done;                      // blocks finished everything
};
__device__ Scratch g_s;

__device__ __forceinline__ long long ld_idx(const void* p, long long i, int is64) {
    if (is64) return ((const long long*)p)[i];
    return (long long)((const int*)p)[i];
}

// ---------------- the one fused kernel ----------------
__global__ void __launch_bounds__(256, 6)
k_all(const float* __restrict__ Ub, const float* __restrict__ U,
      const void* midx, const void* segs, const void* Gp,
      long long N, int P, int PK, double inv_den, float* out, int nb) {
    const int tid = threadIdx.x;
    const int bid = blockIdx.x;

    // ---- dtype probe (warp 0): int32 reinterpreted as int64 -> high word junk
    __shared__ int s_is64;
    if (tid < 32) {
        const long long* p64 = (const long long*)midx;
        int m = (int)(N < 32 ? N : 32);
        int bad = 0;
        if (tid < m) {
            long long v = p64[tid];
            bad = (v < 0 || v >= N) ? 1 : 0;
        }
        unsigned b = __ballot_sync(0xFFFFFFFFu, bad);
        if (tid == 0) s_is64 = (b == 0) ? 1 : 0;
    }
    __syncthreads();
    const int is64 = s_is64;

    // ---- phase H: histogram of G (grid-stride), then publish arrival
    for (int i = bid * 256 + tid; i < PK; i += nb * 256) {
        int g = (int)ld_idx(Gp, i, is64);
        atomicAdd(&g_s.cnt[g], 1.0f);
    }
    __threadfence();
    __syncthreads();
    if (tid == 0) atomicAdd(&g_s.histdone, 1u);

    // ---- phase MW (blocks 0..31 only): M = U U^T, W = U diag(cnt) U^T
    // Overlaps with the other ~880 blocks' dots work.
    if (bid < 32) {
        if (tid == 0) {
            while (*(volatile unsigned*)&g_s.histdone < (unsigned)nb)
                __nanosleep(64);
        }
        __syncthreads();
        __threadfence();

        __shared__ float sh[16][D_DIM];
        __shared__ float shc[16];
        int grp  = bid >> 2;
        int quad = bid & 3;
        int ti = tid & 15, tj = tid >> 4;
        int i0 = (quad & 1) * 64 + ti * 4;
        int j0 = (quad >> 1) * 64 + tj * 4;

        float m[4][4] = {{0}}, w[4][4] = {{0}};
        for (int c = 0; c < 8; c++) {
            int p0 = (grp * 8 + c) * 16;
            __syncthreads();
            for (int e = tid; e < 16 * D_DIM; e += 256) {
                int d = e >> 4, pc = e & 15;
                int p = p0 + pc;
                sh[pc][d] = (p < P) ? U[(size_t)d * P + p] : 0.f;
            }
            if (tid < 16) {
                int p = p0 + tid;
                shc[tid] = (p < P) ? g_s.cnt[p] : 0.f;
            }
            __syncthreads();
#pragma unroll
            for (int pc = 0; pc < 16; pc++) {
                float cw = shc[pc];
                float a[4], ca[4], b[4];
#pragma unroll
                for (int x = 0; x < 4; x++) { a[x] = sh[pc][i0 + x]; ca[x] = cw * a[x]; }
#pragma unroll
                for (int y = 0; y < 4; y++) b[y] = sh[pc][j0 + y];
#pragma unroll
                for (int x = 0; x < 4; x++)
#pragma unroll
                    for (int y = 0; y < 4; y++) {
                        m[x][y] += a[x] * b[y];
                        w[x][y] += ca[x] * b[y];
                    }
            }
        }
#pragma unroll
        for (int x = 0; x < 4; x++)
#pragma unroll
            for (int y = 0; y < 4; y++) {
                int idx = (i0 + x) * D_DIM + (j0 + y);
                atomicAdd(&g_s.M[idx], m[x][y]);
                atomicAdd(&g_s.W[idx], w[x][y]);
            }
    }

    // ---- phase D: dots, pure grid-stride, NO barriers, NO atomics (R1 loop)
    double val = 0.0;
    const long long gstride = (long long)nb * 256;
    for (long long j = (long long)bid * 256 + tid; j < N; j += gstride) {
        long long mi = ld_idx(midx, j, is64);
        int g = (int)ld_idx(segs, j, is64);
        const float* ub = Ub + mi;
        const float* uu = U + g;
        float acc = 0.f;
#pragma unroll 8
        for (int d = 0; d < D_DIM; d++)
            acc += __ldg(ub + (size_t)d * N) * __ldg(uu + (size_t)d * P);
        val += (double)acc * (double)acc;
    }

    // ---- block reduce val (double) and publish
    __shared__ double red[8];
    unsigned mask = 0xFFFFFFFFu;
#pragma unroll
    for (int off = 16; off > 0; off >>= 1)
        val += __shfl_down_sync(mask, val, off);
    int lane = tid & 31, warp = tid >> 5;
    if (lane == 0) red[warp] = val;
    __syncthreads();
    __shared__ int s_last;
    if (tid == 0) s_last = 0;
    __syncthreads();
    if (warp == 0) {
        double s = (lane < 8) ? red[lane] : 0.0;
#pragma unroll
        for (int off = 4; off > 0; off >>= 1)
            s += __shfl_down_sync(mask, s, off);
        if (lane == 0) {
            atomicAdd(&g_s.acc, s);
            __threadfence();
            unsigned t = atomicAdd(&g_s.done, 1u);
            if (t == (unsigned)nb - 1) s_last = 1;
        }
    }
    __syncthreads();

    // ---- last block standing: trace(M .* W) + final writeout
    if (s_last) {
        __threadfence();
        double tr = 0.0;
        int base = tid * 64;                  // 256 threads x 64 elements
#pragma unroll
        for (int q = 0; q < 16; q++) {
            float4 mv = *(const float4*)(g_s.M + base + q * 4);
            float4 wv = *(const float4*)(g_s.W + base + q * 4);
            tr += (double)mv.x * wv.x + (double)mv.y * wv.y
                + (double)mv.z * wv.z + (double)mv.w * wv.w;
        }
#pragma unroll
        for (int off = 16; off > 0; off >>= 1)
            tr += __shfl_down_sync(mask, tr, off);
        if (lane == 0) red[warp] = tr;
        __syncthreads();
        if (warp == 0) {
            double t = (lane < 8) ? red[lane] : 0.0;
#pragma unroll
            for (int off = 4; off > 0; off >>= 1)
                t += __shfl_down_sync(mask, t, off);
            if (lane == 0) {
                double dots_total = *(volatile double*)&g_s.acc;
                out[0] = (float)(-0.5 * dots_total - 0.5 * t * inv_den);
            }
        }
    }
}

// ---------------- launch ----------------
extern "C" void kernel_launch(void* const* d_in, const int* in_sizes, int n_in,
                              void* d_out, int out_size) {
    const float* U_base = (const float*)d_in[0];
    const float* U      = (const float*)d_in[1];
    const void*  midx   = d_in[2];
    const void*  segs   = d_in[3];
    const void*  Gp     = d_in[4];

    long long N = in_sizes[2];
    int D = (int)((long long)in_sizes[0] / N); // = 128
    int P = in_sizes[1] / D;                   // = 1024
    int PK = in_sizes[4];                      // P*K
    int K = PK / P;
    (void)D; (void)n_in;

    float* out = (float*)d_out;
    (void)out_size;

    // Grid sized for guaranteed full co-residency (spin-wait safety).
    int dev = 0, sms = 148, maxb = 6;
    cudaGetDevice(&dev);
    cudaDeviceGetAttribute(&sms, cudaDevAttrMultiProcessorCount, dev);
    cudaOccupancyMaxActiveBlocksPerMultiprocessor(&maxb, k_all, 256, 0);
    int occ = maxb < 6 ? maxb : 6;
    if (occ < 1) occ = 1;
    int nb = sms * occ;
    // MW phase needs at least 32 blocks
    if (nb < 32) nb = 32;

    // Zero ALL scratch with one memset node.
    void* pS;
    cudaGetSymbolAddress(&pS, g_s);
    cudaMemsetAsync(pS, 0, sizeof(Scratch));

    double inv_den = 1.0 / ((double)P * (double)K * (double)P);
    k_all<<<nb, 256>>>(U_base, U, midx, segs, Gp, N, P, PK, inv_den, out, nb);
}

// round 9
// speedup vs baseline: 1.2841x; 1.2841x over previous
#include <cuda_runtime.h>
#include <cstdint>

#define D_DIM 128

// ---------------- device scratch: single struct -> one memset ----------------
struct alignas(16) Scratch {
    float  M[D_DIM * D_DIM];            // M = U U^T            (offset 0)
    float  W[D_DIM * D_DIM];            // W = U diag(cnt) U^T  (offset 64KB)
    float  cnt[4096];                   // histogram of G
    double acc;                         // dots accumulator
    double tr;                          // trace(M .* W), written by k_hmw
    unsigned histdone;                  // k_hmw blocks past hist phase
    unsigned mwdone;                    // k_hmw blocks past MW phase
    unsigned done;                      // k_dots blocks finished
};
__device__ Scratch g_s;

__device__ __forceinline__ long long ld_idx(const void* p, long long i, int is64) {
    if (is64) return ((const long long*)p)[i];
    return (long long)((const int*)p)[i];
}

// Block-level dtype probe: warp 0 reads first <=32 int64 entries of merge_idx.
// int32 data reinterpreted as int64 has nonzero high words -> out of [0,N).
__device__ __forceinline__ int probe_is64(const void* merge_idx, long long N) {
    __shared__ int s_is64;
    if (threadIdx.x < 32) {
        const long long* p64 = (const long long*)merge_idx;
        int m = (int)(N < 32 ? N : 32);
        int bad = 0;
        if ((int)threadIdx.x < m) {
            long long v = p64[threadIdx.x];
            bad = (v < 0 || v >= N) ? 1 : 0;
        }
        unsigned b = __ballot_sync(0xFFFFFFFFu, bad);
        if (threadIdx.x == 0) s_is64 = (b == 0) ? 1 : 0;
    }
    __syncthreads();
    return s_is64;
}

// ---------------- kernel HMW: hist + MW + trace, 32 blocks ----------------
__global__ void __launch_bounds__(256)
k_hmw(const float* __restrict__ U, const void* Gp, const void* midx,
      long long N, int P, int PK) {
    const int tid = threadIdx.x;
    const int bid = blockIdx.x;
    const int is64 = probe_is64(midx, N);

    // ---- phase H: histogram of G (shared-mem when P fits, else global)
    if (P <= 2048) {
        __shared__ unsigned shist[2048];
        for (int p = tid; p < P; p += 256) shist[p] = 0u;
        __syncthreads();
        for (int i = bid * 256 + tid; i < PK; i += 32 * 256) {
            int g = (int)ld_idx(Gp, i, is64);
            atomicAdd(&shist[g], 1u);
        }
        __syncthreads();
        for (int p = tid; p < P; p += 256)
            if (shist[p]) atomicAdd(&g_s.cnt[p], (float)shist[p]);
    } else {
        for (int i = bid * 256 + tid; i < PK; i += 32 * 256) {
            int g = (int)ld_idx(Gp, i, is64);
            atomicAdd(&g_s.cnt[g], 1.0f);
        }
    }
    __threadfence();
    __syncthreads();
    if (tid == 0) atomicAdd(&g_s.histdone, 1u);

    // ---- wait for all 32 blocks' hist (co-resident: 32 <= #SMs)
    if (tid == 0) {
        while (*(volatile unsigned*)&g_s.histdone < 32u)
            __nanosleep(32);
    }
    __syncthreads();
    __threadfence();

    // ---- phase MW: M = U U^T, W = U diag(cnt) U^T
    // 8 groups x 4 quadrants; group handles chunks {grp, grp+8, grp+16, ...}
    {
        __shared__ float sh[16][D_DIM];
        __shared__ float shc[16];
        int grp  = bid >> 2;
        int quad = bid & 3;
        int ti = tid & 15, tj = tid >> 4;
        int i0 = (quad & 1) * 64 + ti * 4;
        int j0 = (quad >> 1) * 64 + tj * 4;
        int nchunk = (P + 15) / 16;

        float m[4][4] = {{0}}, w[4][4] = {{0}};
        for (int c = grp; c < nchunk; c += 8) {
            int p0 = c * 16;
            __syncthreads();
            for (int e = tid; e < 16 * D_DIM; e += 256) {
                int d = e >> 4, pc = e & 15;
                int p = p0 + pc;
                sh[pc][d] = (p < P) ? U[(size_t)d * P + p] : 0.f;
            }
            if (tid < 16) {
                int p = p0 + tid;
                shc[tid] = (p < P) ? g_s.cnt[p] : 0.f;
            }
            __syncthreads();
#pragma unroll
            for (int pc = 0; pc < 16; pc++) {
                float cw = shc[pc];
                float a[4], ca[4], b[4];
#pragma unroll
                for (int x = 0; x < 4; x++) { a[x] = sh[pc][i0 + x]; ca[x] = cw * a[x]; }
#pragma unroll
                for (int y = 0; y < 4; y++) b[y] = sh[pc][j0 + y];
#pragma unroll
                for (int x = 0; x < 4; x++)
#pragma unroll
                    for (int y = 0; y < 4; y++) {
                        m[x][y] += a[x] * b[y];
                        w[x][y] += ca[x] * b[y];
                    }
            }
        }
#pragma unroll
        for (int x = 0; x < 4; x++)
#pragma unroll
            for (int y = 0; y < 4; y++) {
                int idx = (i0 + x) * D_DIM + (j0 + y);
                atomicAdd(&g_s.M[idx], m[x][y]);
                atomicAdd(&g_s.W[idx], w[x][y]);
            }
    }

    // ---- last MW block: trace(M .* W) -> g_s.tr
    __shared__ int s_last;
    if (tid == 0) {
        __threadfence();
        unsigned t = atomicAdd(&g_s.mwdone, 1u);
        s_last = (t == 31u) ? 1 : 0;
    }
    __syncthreads();
    if (s_last) {
        __threadfence();
        double tr = 0.0;
        int base = tid * 64;                  // 256 threads x 64 elements
#pragma unroll
        for (int q = 0; q < 16; q++) {
            float4 mv = *(const float4*)(g_s.M + base + q * 4);
            float4 wv = *(const float4*)(g_s.W + base + q * 4);
            tr += (double)mv.x * wv.x + (double)mv.y * wv.y
                + (double)mv.z * wv.z + (double)mv.w * wv.w;
        }
        __shared__ double red[8];
        unsigned mask = 0xFFFFFFFFu;
#pragma unroll
        for (int off = 16; off > 0; off >>= 1)
            tr += __shfl_down_sync(mask, tr, off);
        int lane = tid & 31, warp = tid >> 5;
        if (lane == 0) red[warp] = tr;
        __syncthreads();
        if (warp == 0) {
            double t = (lane < 8) ? red[lane] : 0.0;
#pragma unroll
            for (int off = 4; off > 0; off >>= 1)
                t += __shfl_down_sync(mask, t, off);
            if (lane == 0) g_s.tr = t;
        }
    }
}

// ---------------- kernel D: R1-form dots + last-block finalize ----------
__global__ void __launch_bounds__(256)
k_dots(const float* __restrict__ Ub, const float* __restrict__ U,
       const void* midx, const void* segs,
       long long N, int P, double inv_den, float* out, int nb) {
    int is64 = probe_is64(midx, N);
    long long j = (long long)blockIdx.x * blockDim.x + threadIdx.x;

    double val = 0.0;
    if (j < N) {
        long long mi = ld_idx(midx, j, is64);
        int g = (int)ld_idx(segs, j, is64);
        const float* ub = Ub + mi;
        const float* uu = U + g;
        float acc = 0.f;
#pragma unroll 8
        for (int d = 0; d < D_DIM; d++)
            acc += __ldg(ub + (size_t)d * N) * __ldg(uu + (size_t)d * P);
        val = (double)acc * (double)acc;
    }

    // block reduce (256 threads) in double
    __shared__ double red[8];
    __shared__ int s_last;
    if (threadIdx.x == 0) s_last = 0;
    unsigned mask = 0xFFFFFFFFu;
#pragma unroll
    for (int off = 16; off > 0; off >>= 1)
        val += __shfl_down_sync(mask, val, off);
    int lane = threadIdx.x & 31, warp = threadIdx.x >> 5;
    if (lane == 0) red[warp] = val;
    __syncthreads();
    if (warp == 0) {
        double s = (lane < 8) ? red[lane] : 0.0;
#pragma unroll
        for (int off = 4; off > 0; off >>= 1)
            s += __shfl_down_sync(mask, s, off);
        if (lane == 0) {
            atomicAdd(&g_s.acc, s);
            __threadfence();
            unsigned t = atomicAdd(&g_s.done, 1u);
            if (t == (unsigned)nb - 1u) s_last = 1;
        }
    }
    __syncthreads();

    // last block standing: combine with precomputed trace and write out
    if (s_last && threadIdx.x == 0) {
        __threadfence();
        double dots_total = *(volatile double*)&g_s.acc;
        double tr = *(volatile double*)&g_s.tr;
        out[0] = (float)(-0.5 * dots_total - 0.5 * tr * inv_den);
    }
}

// ---------------- launch ----------------
extern "C" void kernel_launch(void* const* d_in, const int* in_sizes, int n_in,
                              void* d_out, int out_size) {
    const float* U_base = (const float*)d_in[0];
    const float* U      = (const float*)d_in[1];
    const void*  midx   = d_in[2];
    const void*  segs   = d_in[3];
    const void*  Gp     = d_in[4];

    long long N = in_sizes[2];
    int D = (int)((long long)in_sizes[0] / N); // = 128
    int P = in_sizes[1] / D;                   // = 1024
    int PK = in_sizes[4];                      // P*K
    int K = PK / P;
    (void)D; (void)n_in;

    float* out = (float*)d_out;
    (void)out_size;

    // Zero ALL scratch with one memset node (graph-capturable).
    void* pS;
    cudaGetSymbolAddress(&pS, g_s);
    cudaMemsetAsync(pS, 0, sizeof(Scratch));

    // HMW: hist + MW + trace in one 32-block kernel
    k_hmw<<<32, 256>>>(U, Gp, midx, N, P, PK);

    // D: main HBM-bound pass (R1 form) + inline finalize
    long long nblk = (N + 255) / 256;
    double inv_den = 1.0 / ((double)P * (double)K * (double)P);
    k_dots<<<(unsigned)nblk, 256>>>(U_base, U, midx, segs, N, P, inv_den, out, (int)nblk);
}